// round 8
// baseline (speedup 1.0000x reference)
#include <cuda_runtime.h>
#include <cuda_bf16.h>

#define N_NODES 100000
#define MAX_E   1600000
#define D       128
#define SCAN_BLOCKS ((N_NODES + 255) / 256)   // 391

typedef unsigned int u32;

// ---------------- device scratch ----------------------------------------------
__device__ int   g_cnt[N_NODES];
__device__ int   g_scan[SCAN_BLOCKS * 256];
__device__ int   g_bsum[512];
__device__ int   g_rowptr[N_NODES + 1];
__device__ int   g_cursor[N_NODES];
__device__ int   g_colidx[MAX_E];
__device__ float g_t2[(size_t)N_NODES * 64];   // relu(S(X)@W1+b1) @ W2

// W fragments in mma.sync register layout: [split][kstep][nfrag][lane] uint2
__device__ uint2 g_B1f[2 * 8 * 16 * 32];   // W1: N=128 -> 16 nfrags
__device__ uint2 g_B2f[2 * 8 * 8 * 32];    // W2: N=64  -> 8 nfrags

// ---------------- helpers -------------------------------------------------------
__device__ __forceinline__ u32 pack_bf16(float lo, float hi) {
    __nv_bfloat162 t = __floats2bfloat162_rn(lo, hi);   // .x = lo half
    return *(u32*)&t;
}
__device__ __forceinline__ void mma_bf16(float* c, const u32* a, u32 b0, u32 b1) {
    asm volatile(
        "mma.sync.aligned.m16n8k16.row.col.f32.bf16.bf16.f32 "
        "{%0,%1,%2,%3}, {%4,%5,%6,%7}, {%8,%9}, {%0,%1,%2,%3};"
        : "+f"(c[0]), "+f"(c[1]), "+f"(c[2]), "+f"(c[3])
        : "r"(a[0]), "r"(a[1]), "r"(a[2]), "r"(a[3]), "r"(b0), "r"(b1));
}
__device__ __forceinline__ int edge_idx(const void* p, int i, int is64) {
    return is64 ? (int)((const long long*)p)[i] : ((const int*)p)[i];
}

// ---------------- CSR build -----------------------------------------------------
__global__ void convcount_kernel(const void* __restrict__ dst, int E) {
    int v = ((const int*)dst)[(threadIdx.x & 255) * 2 + 1];
    int is64 = !__syncthreads_or(v != 0);
    int i = blockIdx.x * blockDim.x + threadIdx.x;
    if (i >= E) return;
    int d = edge_idx(dst, i, is64);
    if ((unsigned)d < N_NODES) atomicAdd(&g_cnt[d], 1);
}

__global__ void scan_pass1() {
    __shared__ int s[256];
    int t = threadIdx.x;
    int i = blockIdx.x * 256 + t;
    int v = (i < N_NODES) ? g_cnt[i] : 0;
    s[t] = v;
    __syncthreads();
#pragma unroll
    for (int off = 1; off < 256; off <<= 1) {
        int x = (t >= off) ? s[t - off] : 0;
        __syncthreads();
        s[t] += x;
        __syncthreads();
    }
    g_scan[i] = s[t];
    if (t == 255) g_bsum[blockIdx.x] = s[255];
}

// merged pass 2+3: block-sum prefix via reduction, then finalize rowptr/cursor
__global__ void scan_pass23() {
    const int b = blockIdx.x, t = threadIdx.x;
    int x = 0;
    if (t < b)       x += g_bsum[t];
    if (t + 256 < b) x += g_bsum[t + 256];
#pragma unroll
    for (int o = 16; o > 0; o >>= 1) x += __shfl_down_sync(~0u, x, o);
    __shared__ int wsum[8];
    if ((t & 31) == 0) wsum[t >> 5] = x;
    __syncthreads();
    __shared__ int off;
    if (t == 0) {
        int s = 0;
#pragma unroll
        for (int w = 0; w < 8; w++) s += wsum[w];
        off = s;
    }
    __syncthreads();
    int i = b * 256 + t;
    if (i >= N_NODES) return;
    int incl = g_scan[i] + off;
    g_rowptr[i + 1] = incl;
    g_cursor[i] = incl - g_cnt[i];
    if (i == 0) g_rowptr[0] = 0;
}

__global__ void fill_kernel(const void* __restrict__ src,
                            const void* __restrict__ dst, int E) {
    int v = ((const int*)dst)[(threadIdx.x & 255) * 2 + 1];
    int is64 = !__syncthreads_or(v != 0);
    int i = blockIdx.x * blockDim.x + threadIdx.x;
    if (i >= E) return;
    unsigned d = (unsigned)edge_idx(dst, i, is64);
    unsigned s = (unsigned)edge_idx(src, i, is64);
    if (d >= N_NODES || s >= N_NODES) return;
    int pos = atomicAdd(&g_cursor[d], 1);
    g_colidx[pos] = (int)s;
}

// ---------------- 64-wide mean aggregation + bias epilogue ----------------------
__global__ void agg64_kernel(const float* __restrict__ in,
                             const float* __restrict__ bias,
                             float* __restrict__ out) {
    int warp = (blockIdx.x * blockDim.x + threadIdx.x) >> 5;
    int lane = threadIdx.x & 31;
    if (warp >= N_NODES) return;
    int s = __ldg(&g_rowptr[warp]);
    int e = __ldg(&g_rowptr[warp + 1]);
    float2 acc = make_float2(0.f, 0.f);
    int i = s;
    for (; i + 4 <= e; i += 4) {
        int c0 = __ldg(&g_colidx[i + 0]);
        int c1 = __ldg(&g_colidx[i + 1]);
        int c2 = __ldg(&g_colidx[i + 2]);
        int c3 = __ldg(&g_colidx[i + 3]);
        float2 v0 = __ldg((const float2*)(in + (size_t)c0 * 64) + lane);
        float2 v1 = __ldg((const float2*)(in + (size_t)c1 * 64) + lane);
        float2 v2 = __ldg((const float2*)(in + (size_t)c2 * 64) + lane);
        float2 v3 = __ldg((const float2*)(in + (size_t)c3 * 64) + lane);
        acc.x += (v0.x + v1.x) + (v2.x + v3.x);
        acc.y += (v0.y + v1.y) + (v2.y + v3.y);
    }
    for (; i < e; i++) {
        int c = __ldg(&g_colidx[i]);
        float2 v = __ldg((const float2*)(in + (size_t)c * 64) + lane);
        acc.x += v.x; acc.y += v.y;
    }
    int cnt = e - s;
    float inv = 1.f / (float)(cnt > 1 ? cnt : 1);
    float2 b = __ldg((const float2*)bias + lane);
    float2 o;
    o.x = acc.x * inv + b.x;
    o.y = acc.y * inv + b.y;
    ((float2*)(out + (size_t)warp * 64))[lane] = o;
}

// ---------------- W fp32 -> hi/lo bf16 mma fragments -----------------------------
__global__ void wconv_kernel(const float* __restrict__ W1, const float* __restrict__ W2) {
    int i = blockIdx.x * blockDim.x + threadIdx.x;
    if (i < 4096) {                          // W1: 8 ks x 16 nf x 32 lanes
        int lane = i & 31, nf = (i >> 5) & 15, ks = i >> 9;
        int k = ks * 16 + (lane & 3) * 2;
        int n = nf * 8 + (lane >> 2);
        float w00 = W1[k * 128 + n],       w01 = W1[(k + 1) * 128 + n];
        float w10 = W1[(k + 8) * 128 + n], w11 = W1[(k + 9) * 128 + n];
        float h00 = __bfloat162float(__float2bfloat16(w00));
        float h01 = __bfloat162float(__float2bfloat16(w01));
        float h10 = __bfloat162float(__float2bfloat16(w10));
        float h11 = __bfloat162float(__float2bfloat16(w11));
        uint2 hi, lo;
        hi.x = pack_bf16(h00, h01);          hi.y = pack_bf16(h10, h11);
        lo.x = pack_bf16(w00 - h00, w01 - h01);
        lo.y = pack_bf16(w10 - h10, w11 - h11);
        g_B1f[(ks * 16 + nf) * 32 + lane]       = hi;
        g_B1f[((8 + ks) * 16 + nf) * 32 + lane] = lo;
    } else if (i < 6144) {                   // W2: 8 ks x 8 nf x 32 lanes
        int j = i - 4096;
        int lane = j & 31, nf = (j >> 5) & 7, ks = j >> 8;
        int k = ks * 16 + (lane & 3) * 2;
        int n = nf * 8 + (lane >> 2);
        float w00 = W2[k * 64 + n],       w01 = W2[(k + 1) * 64 + n];
        float w10 = W2[(k + 8) * 64 + n], w11 = W2[(k + 9) * 64 + n];
        float h00 = __bfloat162float(__float2bfloat16(w00));
        float h01 = __bfloat162float(__float2bfloat16(w01));
        float h10 = __bfloat162float(__float2bfloat16(w10));
        float h11 = __bfloat162float(__float2bfloat16(w11));
        uint2 hi, lo;
        hi.x = pack_bf16(h00, h01);          hi.y = pack_bf16(h10, h11);
        lo.x = pack_bf16(w00 - h00, w01 - h01);
        lo.y = pack_bf16(w10 - h10, w11 - h11);
        g_B2f[(ks * 8 + nf) * 32 + lane]       = hi;
        g_B2f[((8 + ks) * 8 + nf) * 32 + lane] = lo;
    }
}

// ---------------- mega kernel: gather-mean + relu(.@W1+b1)@W2 --------------------
// Per CTA: 128 nodes. Warps gather/average their rows directly from features into
// the smem A-tile (hi/lo bf16), then two HMMA stages produce t2 rows.
#define ASTRIDE 68
#define SM_B1   0                            // 512 B bias
#define SM_AHI  512
#define SM_ALO  (SM_AHI + 34816)
#define SM_BF1  (SM_ALO + 34816)
#define SM_BF2  (SM_BF1 + 65536)
#define SM_TOT  (SM_BF2 + 32768)             // 168448

__global__ void __launch_bounds__(256, 1)
mega_kernel(const float* __restrict__ X, const float* __restrict__ b1,
            float* __restrict__ T2) {
    extern __shared__ char smem[];
    float* b1s = (float*)(smem + SM_B1);
    u32*   Ahi = (u32*)(smem + SM_AHI);
    u32*   Alo = (u32*)(smem + SM_ALO);
    uint2* Bs1 = (uint2*)(smem + SM_BF1);
    uint2* Bs2 = (uint2*)(smem + SM_BF2);

    const int tid  = threadIdx.x;
    const int lane = tid & 31;
    const int wid  = tid >> 5;
    const int wm   = wid & 3;
    const int wn   = wid >> 2;
    const int m0   = blockIdx.x * 128;

    // stage B fragments + bias
    {
        const uint4* s1 = (const uint4*)g_B1f;
        const uint4* s2 = (const uint4*)g_B2f;
        uint4* d1 = (uint4*)Bs1;
        uint4* d2 = (uint4*)Bs2;
        for (int i = tid; i < 4096; i += 256) d1[i] = s1[i];
        for (int i = tid; i < 2048; i += 256) d2[i] = s2[i];
        if (tid < 32) ((float4*)b1s)[tid] = ((const float4*)b1)[tid];
    }

    // gather-mean 128 rows directly into A tile (one warp per row, 16 rows/warp)
    for (int rr = wid; rr < 128; rr += 8) {
        int m = m0 + rr;
        float4 acc = make_float4(0.f, 0.f, 0.f, 0.f);
        if (m < N_NODES) {
            int s = __ldg(&g_rowptr[m]);
            int e = __ldg(&g_rowptr[m + 1]);
            int i = s;
            for (; i + 4 <= e; i += 4) {
                int c0 = __ldg(&g_colidx[i + 0]);
                int c1 = __ldg(&g_colidx[i + 1]);
                int c2 = __ldg(&g_colidx[i + 2]);
                int c3 = __ldg(&g_colidx[i + 3]);
                float4 v0 = __ldg((const float4*)(X + (size_t)c0 * D) + lane);
                float4 v1 = __ldg((const float4*)(X + (size_t)c1 * D) + lane);
                float4 v2 = __ldg((const float4*)(X + (size_t)c2 * D) + lane);
                float4 v3 = __ldg((const float4*)(X + (size_t)c3 * D) + lane);
                acc.x += (v0.x + v1.x) + (v2.x + v3.x);
                acc.y += (v0.y + v1.y) + (v2.y + v3.y);
                acc.z += (v0.z + v1.z) + (v2.z + v3.z);
                acc.w += (v0.w + v1.w) + (v2.w + v3.w);
            }
            for (; i < e; i++) {
                int c = __ldg(&g_colidx[i]);
                float4 v = __ldg((const float4*)(X + (size_t)c * D) + lane);
                acc.x += v.x; acc.y += v.y; acc.z += v.z; acc.w += v.w;
            }
            int cnt = e - s;
            float inv = 1.f / (float)(cnt > 1 ? cnt : 1);
            acc.x *= inv; acc.y *= inv; acc.z *= inv; acc.w *= inv;
        }
        // convert to hi/lo bf16, store into padded A tile (cols lane*4..+3)
        float hx = __bfloat162float(__float2bfloat16(acc.x));
        float hy = __bfloat162float(__float2bfloat16(acc.y));
        float hz = __bfloat162float(__float2bfloat16(acc.z));
        float hw = __bfloat162float(__float2bfloat16(acc.w));
        uint2 hp, lp;
        hp.x = pack_bf16(hx, hy);               hp.y = pack_bf16(hz, hw);
        lp.x = pack_bf16(acc.x - hx, acc.y - hy);
        lp.y = pack_bf16(acc.z - hz, acc.w - hw);
        *(uint2*)&Ahi[rr * ASTRIDE + lane * 2] = hp;
        *(uint2*)&Alo[rr * ASTRIDE + lane * 2] = lp;
    }
    __syncthreads();

    // ---------------- stage 1: D1 = S @ W1  (M128 x N128) -----------------------
    float acc[2][8][4];
#pragma unroll
    for (int mf = 0; mf < 2; mf++)
#pragma unroll
        for (int nf = 0; nf < 8; nf++)
#pragma unroll
            for (int q = 0; q < 4; q++) acc[mf][nf][q] = 0.f;

    const int arow = (lane >> 2);
    const int acol = (lane & 3);
#pragma unroll
    for (int ks = 0; ks < 8; ks++) {
        int cb = ks * 8 + acol;
        u32 ah[2][4], al[2][4];
#pragma unroll
        for (int mf = 0; mf < 2; mf++) {
            int r = wm * 32 + mf * 16 + arow;
            ah[mf][0] = Ahi[r * ASTRIDE + cb];
            ah[mf][1] = Ahi[(r + 8) * ASTRIDE + cb];
            ah[mf][2] = Ahi[r * ASTRIDE + cb + 4];
            ah[mf][3] = Ahi[(r + 8) * ASTRIDE + cb + 4];
            al[mf][0] = Alo[r * ASTRIDE + cb];
            al[mf][1] = Alo[(r + 8) * ASTRIDE + cb];
            al[mf][2] = Alo[r * ASTRIDE + cb + 4];
            al[mf][3] = Alo[(r + 8) * ASTRIDE + cb + 4];
        }
#pragma unroll
        for (int nf = 0; nf < 8; nf++) {
            int nfg = wn * 8 + nf;
            uint2 bh = Bs1[(ks * 16 + nfg) * 32 + lane];
            uint2 bl = Bs1[((8 + ks) * 16 + nfg) * 32 + lane];
#pragma unroll
            for (int mf = 0; mf < 2; mf++) {
                mma_bf16(acc[mf][nf], ah[mf], bh.x, bh.y);
                mma_bf16(acc[mf][nf], ah[mf], bl.x, bl.y);
                mma_bf16(acc[mf][nf], al[mf], bh.x, bh.y);
            }
        }
    }
    __syncthreads();   // all stage-1 A reads complete before overwrite

    // epilogue 1: h1 = relu(D1 + b1) -> hi/lo bf16 back into A smem
#pragma unroll
    for (int mf = 0; mf < 2; mf++) {
#pragma unroll
        for (int nf = 0; nf < 8; nf++) {
            int r   = wm * 32 + mf * 16 + arow;
            int col = wn * 64 + nf * 8 + acol * 2;
            float bb0 = b1s[col], bb1 = b1s[col + 1];
            float x0 = fmaxf(acc[mf][nf][0] + bb0, 0.f);
            float x1 = fmaxf(acc[mf][nf][1] + bb1, 0.f);
            float x2 = fmaxf(acc[mf][nf][2] + bb0, 0.f);
            float x3 = fmaxf(acc[mf][nf][3] + bb1, 0.f);
            float h0 = __bfloat162float(__float2bfloat16(x0));
            float h1 = __bfloat162float(__float2bfloat16(x1));
            float h2 = __bfloat162float(__float2bfloat16(x2));
            float h3 = __bfloat162float(__float2bfloat16(x3));
            Ahi[r * ASTRIDE + (col >> 1)]       = pack_bf16(h0, h1);
            Alo[r * ASTRIDE + (col >> 1)]       = pack_bf16(x0 - h0, x1 - h1);
            Ahi[(r + 8) * ASTRIDE + (col >> 1)] = pack_bf16(h2, h3);
            Alo[(r + 8) * ASTRIDE + (col >> 1)] = pack_bf16(x2 - h2, x3 - h3);
        }
    }
    __syncthreads();

    // ---------------- stage 2: t2 = h1 @ W2  (M128 x N64) -----------------------
    float acc2[2][4][4];
#pragma unroll
    for (int mf = 0; mf < 2; mf++)
#pragma unroll
        for (int nf = 0; nf < 4; nf++)
#pragma unroll
            for (int q = 0; q < 4; q++) acc2[mf][nf][q] = 0.f;

#pragma unroll
    for (int ks = 0; ks < 8; ks++) {
        int cb = ks * 8 + acol;
        u32 ah[2][4], al[2][4];
#pragma unroll
        for (int mf = 0; mf < 2; mf++) {
            int r = wm * 32 + mf * 16 + arow;
            ah[mf][0] = Ahi[r * ASTRIDE + cb];
            ah[mf][1] = Ahi[(r + 8) * ASTRIDE + cb];
            ah[mf][2] = Ahi[r * ASTRIDE + cb + 4];
            ah[mf][3] = Ahi[(r + 8) * ASTRIDE + cb + 4];
            al[mf][0] = Alo[r * ASTRIDE + cb];
            al[mf][1] = Alo[(r + 8) * ASTRIDE + cb];
            al[mf][2] = Alo[r * ASTRIDE + cb + 4];
            al[mf][3] = Alo[(r + 8) * ASTRIDE + cb + 4];
        }
#pragma unroll
        for (int nf = 0; nf < 4; nf++) {
            int nfg = wn * 4 + nf;
            uint2 bh = Bs2[(ks * 8 + nfg) * 32 + lane];
            uint2 bl = Bs2[((8 + ks) * 8 + nfg) * 32 + lane];
#pragma unroll
            for (int mf = 0; mf < 2; mf++) {
                mma_bf16(acc2[mf][nf], ah[mf], bh.x, bh.y);
                mma_bf16(acc2[mf][nf], ah[mf], bl.x, bl.y);
                mma_bf16(acc2[mf][nf], al[mf], bh.x, bh.y);
            }
        }
    }

    // epilogue 2: write t2
#pragma unroll
    for (int mf = 0; mf < 2; mf++) {
#pragma unroll
        for (int nf = 0; nf < 4; nf++) {
            int r   = m0 + wm * 32 + mf * 16 + arow;
            int col = wn * 32 + nf * 8 + acol * 2;
            if (r < N_NODES)
                *(float2*)&g_t2[(size_t)r * 64 + col] =
                    make_float2(acc2[mf][nf][0], acc2[mf][nf][1]);
            if (r + 8 < N_NODES)
                *(float2*)&g_t2[(size_t)(r + 8) * 64 + col] =
                    make_float2(acc2[mf][nf][2], acc2[mf][nf][3]);
        }
    }
    (void)T2;
}

// ---------------- launch ---------------------------------------------------------
extern "C" void kernel_launch(void* const* d_in, const int* in_sizes, int n_in,
                              void* d_out, int out_size) {
    const float* features = (const float*)d_in[0];
    const float* W1       = (const float*)d_in[1];
    const float* b1       = (const float*)d_in[2];
    const float* W2       = (const float*)d_in[3];
    const float* b2       = (const float*)d_in[4];
    const void*  src      = d_in[5];
    const void*  dst      = d_in[6];
    float*       out      = (float*)d_out;
    int E = in_sizes[5];
    if (E > MAX_E) E = MAX_E;

    float *t2_p;
    int   *cnt_p;
    cudaGetSymbolAddress((void**)&t2_p,  g_t2);
    cudaGetSymbolAddress((void**)&cnt_p, g_cnt);

    cudaFuncSetAttribute(mega_kernel,
                         cudaFuncAttributeMaxDynamicSharedMemorySize, SM_TOT);

    const int TB = 256;
    cudaMemsetAsync(cnt_p, 0, N_NODES * sizeof(int), 0);
    wconv_kernel<<<24, 256>>>(W1, W2);
    convcount_kernel<<<(E + TB - 1) / TB, TB>>>(dst, E);
    scan_pass1<<<SCAN_BLOCKS, 256>>>();
    scan_pass23<<<SCAN_BLOCKS, 256>>>();
    fill_kernel<<<(E + TB - 1) / TB, TB>>>(src, dst, E);

    mega_kernel<<<(N_NODES + 127) / 128, 256, SM_TOT>>>(features, b1, t2_p);

    int agg_blocks = (N_NODES * 32 + TB - 1) / TB;
    agg64_kernel<<<agg_blocks, TB>>>(t2_p, b2, out);
}

// round 9
// speedup vs baseline: 1.3405x; 1.3405x over previous
#include <cuda_runtime.h>
#include <cuda_bf16.h>

#define N_NODES 100000
#define MAX_E   1600000
#define D       128
#define SCAN_BLOCKS ((N_NODES + 255) / 256)   // 391

typedef unsigned int u32;

// ---------------- device scratch ----------------------------------------------
__device__ int   g_cnt[N_NODES];
__device__ int   g_scan[SCAN_BLOCKS * 256];
__device__ int   g_bsum[512];
__device__ int   g_rowptr[N_NODES + 1];
__device__ int   g_cursor[N_NODES];
__device__ int   g_colidx[MAX_E];
__device__ float g_agg[(size_t)N_NODES * D];   // S(X), 128-wide
__device__ float g_t2 [(size_t)N_NODES * 64];  // relu(S(X)@W1+b1) @ W2

// W fragments in mma.sync register layout: [split][kstep][nfrag][lane] uint2
__device__ uint2 g_B1f[2 * 8 * 16 * 32];   // W1: N=128 -> 16 nfrags
__device__ uint2 g_B2f[2 * 8 * 8 * 32];    // W2: N=64  -> 8 nfrags

// ---------------- helpers -------------------------------------------------------
__device__ __forceinline__ u32 pack_bf16(float lo, float hi) {
    __nv_bfloat162 t = __floats2bfloat162_rn(lo, hi);   // .x = lo half
    return *(u32*)&t;
}
__device__ __forceinline__ void mma_bf16(float* c, const u32* a, u32 b0, u32 b1) {
    asm volatile(
        "mma.sync.aligned.m16n8k16.row.col.f32.bf16.bf16.f32 "
        "{%0,%1,%2,%3}, {%4,%5,%6,%7}, {%8,%9}, {%0,%1,%2,%3};"
        : "+f"(c[0]), "+f"(c[1]), "+f"(c[2]), "+f"(c[3])
        : "r"(a[0]), "r"(a[1]), "r"(a[2]), "r"(a[3]), "r"(b0), "r"(b1));
}
__device__ __forceinline__ int edge_idx(const void* p, int i, int is64) {
    return is64 ? (int)((const long long*)p)[i] : ((const int*)p)[i];
}

// ---------------- CSR build -----------------------------------------------------
__global__ void convcount_kernel(const void* __restrict__ dst, int E) {
    int v = ((const int*)dst)[(threadIdx.x & 255) * 2 + 1];
    int is64 = !__syncthreads_or(v != 0);
    int i = blockIdx.x * blockDim.x + threadIdx.x;
    if (i >= E) return;
    int d = edge_idx(dst, i, is64);
    if ((unsigned)d < N_NODES) atomicAdd(&g_cnt[d], 1);
}

__global__ void scan_pass1() {
    __shared__ int s[256];
    int t = threadIdx.x;
    int i = blockIdx.x * 256 + t;
    int v = (i < N_NODES) ? g_cnt[i] : 0;
    s[t] = v;
    __syncthreads();
#pragma unroll
    for (int off = 1; off < 256; off <<= 1) {
        int x = (t >= off) ? s[t - off] : 0;
        __syncthreads();
        s[t] += x;
        __syncthreads();
    }
    g_scan[i] = s[t];
    if (t == 255) g_bsum[blockIdx.x] = s[255];
}

// merged pass 2+3: block-sum prefix via reduction, then finalize rowptr/cursor
__global__ void scan_pass23() {
    const int b = blockIdx.x, t = threadIdx.x;
    int x = 0;
    if (t < b)       x += g_bsum[t];
    if (t + 256 < b) x += g_bsum[t + 256];
#pragma unroll
    for (int o = 16; o > 0; o >>= 1) x += __shfl_down_sync(~0u, x, o);
    __shared__ int wsum[8];
    if ((t & 31) == 0) wsum[t >> 5] = x;
    __syncthreads();
    __shared__ int off;
    if (t == 0) {
        int s = 0;
#pragma unroll
        for (int w = 0; w < 8; w++) s += wsum[w];
        off = s;
    }
    __syncthreads();
    int i = b * 256 + t;
    if (i >= N_NODES) return;
    int incl = g_scan[i] + off;
    g_rowptr[i + 1] = incl;
    g_cursor[i] = incl - g_cnt[i];
    if (i == 0) g_rowptr[0] = 0;
}

__global__ void fill_kernel(const void* __restrict__ src,
                            const void* __restrict__ dst, int E) {
    int v = ((const int*)dst)[(threadIdx.x & 255) * 2 + 1];
    int is64 = !__syncthreads_or(v != 0);
    int i = blockIdx.x * blockDim.x + threadIdx.x;
    if (i >= E) return;
    unsigned d = (unsigned)edge_idx(dst, i, is64);
    unsigned s = (unsigned)edge_idx(src, i, is64);
    if (d >= N_NODES || s >= N_NODES) return;
    int pos = atomicAdd(&g_cursor[d], 1);
    g_colidx[pos] = (int)s;
}

// ---------------- aggregations ---------------------------------------------------
__global__ void agg_kernel(const float* __restrict__ in, float* __restrict__ out) {
    int warp = (blockIdx.x * blockDim.x + threadIdx.x) >> 5;
    int lane = threadIdx.x & 31;
    if (warp >= N_NODES) return;
    int s = __ldg(&g_rowptr[warp]);
    int e = __ldg(&g_rowptr[warp + 1]);
    float4 acc = make_float4(0.f, 0.f, 0.f, 0.f);
    int i = s;
    for (; i + 4 <= e; i += 4) {
        int c0 = __ldg(&g_colidx[i + 0]);
        int c1 = __ldg(&g_colidx[i + 1]);
        int c2 = __ldg(&g_colidx[i + 2]);
        int c3 = __ldg(&g_colidx[i + 3]);
        float4 v0 = __ldg((const float4*)(in + (size_t)c0 * D) + lane);
        float4 v1 = __ldg((const float4*)(in + (size_t)c1 * D) + lane);
        float4 v2 = __ldg((const float4*)(in + (size_t)c2 * D) + lane);
        float4 v3 = __ldg((const float4*)(in + (size_t)c3 * D) + lane);
        acc.x += (v0.x + v1.x) + (v2.x + v3.x);
        acc.y += (v0.y + v1.y) + (v2.y + v3.y);
        acc.z += (v0.z + v1.z) + (v2.z + v3.z);
        acc.w += (v0.w + v1.w) + (v2.w + v3.w);
    }
    for (; i < e; i++) {
        int c = __ldg(&g_colidx[i]);
        float4 v = __ldg((const float4*)(in + (size_t)c * D) + lane);
        acc.x += v.x; acc.y += v.y; acc.z += v.z; acc.w += v.w;
    }
    int cnt = e - s;
    float inv = 1.f / (float)(cnt > 1 ? cnt : 1);
    acc.x *= inv; acc.y *= inv; acc.z *= inv; acc.w *= inv;
    ((float4*)(out + (size_t)warp * D))[lane] = acc;
}

__global__ void agg64_kernel(const float* __restrict__ in,
                             const float* __restrict__ bias,
                             float* __restrict__ out) {
    int warp = (blockIdx.x * blockDim.x + threadIdx.x) >> 5;
    int lane = threadIdx.x & 31;
    if (warp >= N_NODES) return;
    int s = __ldg(&g_rowptr[warp]);
    int e = __ldg(&g_rowptr[warp + 1]);
    float2 acc = make_float2(0.f, 0.f);
    int i = s;
    for (; i + 4 <= e; i += 4) {
        int c0 = __ldg(&g_colidx[i + 0]);
        int c1 = __ldg(&g_colidx[i + 1]);
        int c2 = __ldg(&g_colidx[i + 2]);
        int c3 = __ldg(&g_colidx[i + 3]);
        float2 v0 = __ldg((const float2*)(in + (size_t)c0 * 64) + lane);
        float2 v1 = __ldg((const float2*)(in + (size_t)c1 * 64) + lane);
        float2 v2 = __ldg((const float2*)(in + (size_t)c2 * 64) + lane);
        float2 v3 = __ldg((const float2*)(in + (size_t)c3 * 64) + lane);
        acc.x += (v0.x + v1.x) + (v2.x + v3.x);
        acc.y += (v0.y + v1.y) + (v2.y + v3.y);
    }
    for (; i < e; i++) {
        int c = __ldg(&g_colidx[i]);
        float2 v = __ldg((const float2*)(in + (size_t)c * 64) + lane);
        acc.x += v.x; acc.y += v.y;
    }
    int cnt = e - s;
    float inv = 1.f / (float)(cnt > 1 ? cnt : 1);
    float2 b = __ldg((const float2*)bias + lane);
    float2 o;
    o.x = acc.x * inv + b.x;
    o.y = acc.y * inv + b.y;
    ((float2*)(out + (size_t)warp * 64))[lane] = o;
}

// ---------------- W fp32 -> hi/lo bf16 mma fragments -----------------------------
__global__ void wconv_kernel(const float* __restrict__ W1, const float* __restrict__ W2) {
    int i = blockIdx.x * blockDim.x + threadIdx.x;
    if (i < 4096) {                          // W1: 8 ks x 16 nf x 32 lanes
        int lane = i & 31, nf = (i >> 5) & 15, ks = i >> 9;
        int k = ks * 16 + (lane & 3) * 2;
        int n = nf * 8 + (lane >> 2);
        float w00 = W1[k * 128 + n],       w01 = W1[(k + 1) * 128 + n];
        float w10 = W1[(k + 8) * 128 + n], w11 = W1[(k + 9) * 128 + n];
        float h00 = __bfloat162float(__float2bfloat16(w00));
        float h01 = __bfloat162float(__float2bfloat16(w01));
        float h10 = __bfloat162float(__float2bfloat16(w10));
        float h11 = __bfloat162float(__float2bfloat16(w11));
        uint2 hi, lo;
        hi.x = pack_bf16(h00, h01);          hi.y = pack_bf16(h10, h11);
        lo.x = pack_bf16(w00 - h00, w01 - h01);
        lo.y = pack_bf16(w10 - h10, w11 - h11);
        g_B1f[(ks * 16 + nf) * 32 + lane]       = hi;
        g_B1f[((8 + ks) * 16 + nf) * 32 + lane] = lo;
    } else if (i < 6144) {                   // W2: 8 ks x 8 nf x 32 lanes
        int j = i - 4096;
        int lane = j & 31, nf = (j >> 5) & 7, ks = j >> 8;
        int k = ks * 16 + (lane & 3) * 2;
        int n = nf * 8 + (lane >> 2);
        float w00 = W2[k * 64 + n],       w01 = W2[(k + 1) * 64 + n];
        float w10 = W2[(k + 8) * 64 + n], w11 = W2[(k + 9) * 64 + n];
        float h00 = __bfloat162float(__float2bfloat16(w00));
        float h01 = __bfloat162float(__float2bfloat16(w01));
        float h10 = __bfloat162float(__float2bfloat16(w10));
        float h11 = __bfloat162float(__float2bfloat16(w11));
        uint2 hi, lo;
        hi.x = pack_bf16(h00, h01);          hi.y = pack_bf16(h10, h11);
        lo.x = pack_bf16(w00 - h00, w01 - h01);
        lo.y = pack_bf16(w10 - h10, w11 - h11);
        g_B2f[(ks * 8 + nf) * 32 + lane]       = hi;
        g_B2f[((8 + ks) * 8 + nf) * 32 + lane] = lo;
    }
}

// ---------------- fused double GEMM via HMMA (3x bf16 split) ---------------------
// t2 = relu(A @ W1 + b1) @ W2. CTA = 128 rows, 256 thr (8 warps, 4Mx2N grid).
// A tile stored hi/lo bf16 in smem, padded row stride 68 u32 (136 halves).
#define ASTRIDE 68
#define SM_B1   0                            // 512 B bias
#define SM_AHI  512
#define SM_ALO  (SM_AHI + 34816)
#define SM_BF1  (SM_ALO + 34816)
#define SM_BF2  (SM_BF1 + 65536)
#define SM_TOT  (SM_BF2 + 32768)             // 168448

__global__ void __launch_bounds__(256, 1)
gemm_hmma_kernel(const float* __restrict__ A, const float* __restrict__ b1,
                 float* __restrict__ T2) {
    extern __shared__ char smem[];
    float* b1s = (float*)(smem + SM_B1);
    u32*   Ahi = (u32*)(smem + SM_AHI);
    u32*   Alo = (u32*)(smem + SM_ALO);
    uint2* Bs1 = (uint2*)(smem + SM_BF1);
    uint2* Bs2 = (uint2*)(smem + SM_BF2);

    const int tid  = threadIdx.x;
    const int lane = tid & 31;
    const int wid  = tid >> 5;
    const int wm   = wid & 3;
    const int wn   = wid >> 2;
    const int m0   = blockIdx.x * 128;

    {
        const uint4* s1 = (const uint4*)g_B1f;
        const uint4* s2 = (const uint4*)g_B2f;
        uint4* d1 = (uint4*)Bs1;
        uint4* d2 = (uint4*)Bs2;
        for (int i = tid; i < 4096; i += 256) d1[i] = s1[i];
        for (int i = tid; i < 2048; i += 256) d2[i] = s2[i];
        if (tid < 32) ((float4*)b1s)[tid] = ((const float4*)b1)[tid];
    }

    for (int i = tid * 4; i < 16384; i += 1024) {
        int r = i >> 7, c = i & 127;
        float4 v = make_float4(0.f, 0.f, 0.f, 0.f);
        if (m0 + r < N_NODES)
            v = *(const float4*)&A[(size_t)(m0 + r) * 128 + c];
        float hx = __bfloat162float(__float2bfloat16(v.x));
        float hy = __bfloat162float(__float2bfloat16(v.y));
        float hz = __bfloat162float(__float2bfloat16(v.z));
        float hw = __bfloat162float(__float2bfloat16(v.w));
        uint2 hp, lp;
        hp.x = pack_bf16(hx, hy);             hp.y = pack_bf16(hz, hw);
        lp.x = pack_bf16(v.x - hx, v.y - hy); lp.y = pack_bf16(v.z - hz, v.w - hw);
        *(uint2*)&Ahi[r * ASTRIDE + (c >> 1)] = hp;
        *(uint2*)&Alo[r * ASTRIDE + (c >> 1)] = lp;
    }
    __syncthreads();

    // ---------------- stage 1: D1 = A @ W1  (M128 x N128) -----------------------
    float acc[2][8][4];
#pragma unroll
    for (int mf = 0; mf < 2; mf++)
#pragma unroll
        for (int nf = 0; nf < 8; nf++)
#pragma unroll
            for (int q = 0; q < 4; q++) acc[mf][nf][q] = 0.f;

    const int arow = (lane >> 2);
    const int acol = (lane & 3);
#pragma unroll
    for (int ks = 0; ks < 8; ks++) {
        int cb = ks * 8 + acol;
        u32 ah[2][4], al[2][4];
#pragma unroll
        for (int mf = 0; mf < 2; mf++) {
            int r = wm * 32 + mf * 16 + arow;
            ah[mf][0] = Ahi[r * ASTRIDE + cb];
            ah[mf][1] = Ahi[(r + 8) * ASTRIDE + cb];
            ah[mf][2] = Ahi[r * ASTRIDE + cb + 4];
            ah[mf][3] = Ahi[(r + 8) * ASTRIDE + cb + 4];
            al[mf][0] = Alo[r * ASTRIDE + cb];
            al[mf][1] = Alo[(r + 8) * ASTRIDE + cb];
            al[mf][2] = Alo[r * ASTRIDE + cb + 4];
            al[mf][3] = Alo[(r + 8) * ASTRIDE + cb + 4];
        }
#pragma unroll
        for (int nf = 0; nf < 8; nf++) {
            int nfg = wn * 8 + nf;
            uint2 bh = Bs1[(ks * 16 + nfg) * 32 + lane];
            uint2 bl = Bs1[((8 + ks) * 16 + nfg) * 32 + lane];
#pragma unroll
            for (int mf = 0; mf < 2; mf++) {
                mma_bf16(acc[mf][nf], ah[mf], bh.x, bh.y);
                mma_bf16(acc[mf][nf], ah[mf], bl.x, bl.y);
                mma_bf16(acc[mf][nf], al[mf], bh.x, bh.y);
            }
        }
    }
    __syncthreads();   // all stage-1 A reads complete before overwrite

    // epilogue 1: h1 = relu(D1 + b1) -> hi/lo bf16 back into A smem
#pragma unroll
    for (int mf = 0; mf < 2; mf++) {
#pragma unroll
        for (int nf = 0; nf < 8; nf++) {
            int r   = wm * 32 + mf * 16 + arow;
            int col = wn * 64 + nf * 8 + acol * 2;
            float bb0 = b1s[col], bb1 = b1s[col + 1];
            float x0 = fmaxf(acc[mf][nf][0] + bb0, 0.f);
            float x1 = fmaxf(acc[mf][nf][1] + bb1, 0.f);
            float x2 = fmaxf(acc[mf][nf][2] + bb0, 0.f);
            float x3 = fmaxf(acc[mf][nf][3] + bb1, 0.f);
            float h0 = __bfloat162float(__float2bfloat16(x0));
            float h1 = __bfloat162float(__float2bfloat16(x1));
            float h2 = __bfloat162float(__float2bfloat16(x2));
            float h3 = __bfloat162float(__float2bfloat16(x3));
            Ahi[r * ASTRIDE + (col >> 1)]       = pack_bf16(h0, h1);
            Alo[r * ASTRIDE + (col >> 1)]       = pack_bf16(x0 - h0, x1 - h1);
            Ahi[(r + 8) * ASTRIDE + (col >> 1)] = pack_bf16(h2, h3);
            Alo[(r + 8) * ASTRIDE + (col >> 1)] = pack_bf16(x2 - h2, x3 - h3);
        }
    }
    __syncthreads();

    // ---------------- stage 2: t2 = h1 @ W2  (M128 x N64) -----------------------
    float acc2[2][4][4];
#pragma unroll
    for (int mf = 0; mf < 2; mf++)
#pragma unroll
        for (int nf = 0; nf < 4; nf++)
#pragma unroll
            for (int q = 0; q < 4; q++) acc2[mf][nf][q] = 0.f;

#pragma unroll
    for (int ks = 0; ks < 8; ks++) {
        int cb = ks * 8 + acol;
        u32 ah[2][4], al[2][4];
#pragma unroll
        for (int mf = 0; mf < 2; mf++) {
            int r = wm * 32 + mf * 16 + arow;
            ah[mf][0] = Ahi[r * ASTRIDE + cb];
            ah[mf][1] = Ahi[(r + 8) * ASTRIDE + cb];
            ah[mf][2] = Ahi[r * ASTRIDE + cb + 4];
            ah[mf][3] = Ahi[(r + 8) * ASTRIDE + cb + 4];
            al[mf][0] = Alo[r * ASTRIDE + cb];
            al[mf][1] = Alo[(r + 8) * ASTRIDE + cb];
            al[mf][2] = Alo[r * ASTRIDE + cb + 4];
            al[mf][3] = Alo[(r + 8) * ASTRIDE + cb + 4];
        }
#pragma unroll
        for (int nf = 0; nf < 4; nf++) {
            int nfg = wn * 4 + nf;
            uint2 bh = Bs2[(ks * 8 + nfg) * 32 + lane];
            uint2 bl = Bs2[((8 + ks) * 8 + nfg) * 32 + lane];
#pragma unroll
            for (int mf = 0; mf < 2; mf++) {
                mma_bf16(acc2[mf][nf], ah[mf], bh.x, bh.y);
                mma_bf16(acc2[mf][nf], ah[mf], bl.x, bl.y);
                mma_bf16(acc2[mf][nf], al[mf], bh.x, bh.y);
            }
        }
    }

    // epilogue 2: write t2
#pragma unroll
    for (int mf = 0; mf < 2; mf++) {
#pragma unroll
        for (int nf = 0; nf < 4; nf++) {
            int r   = m0 + wm * 32 + mf * 16 + arow;
            int col = wn * 32 + nf * 8 + acol * 2;
            if (r < N_NODES)
                *(float2*)&T2[(size_t)r * 64 + col] =
                    make_float2(acc2[mf][nf][0], acc2[mf][nf][1]);
            if (r + 8 < N_NODES)
                *(float2*)&T2[(size_t)(r + 8) * 64 + col] =
                    make_float2(acc2[mf][nf][2], acc2[mf][nf][3]);
        }
    }
}

// ---------------- launch ---------------------------------------------------------
extern "C" void kernel_launch(void* const* d_in, const int* in_sizes, int n_in,
                              void* d_out, int out_size) {
    const float* features = (const float*)d_in[0];
    const float* W1       = (const float*)d_in[1];
    const float* b1       = (const float*)d_in[2];
    const float* W2       = (const float*)d_in[3];
    const float* b2       = (const float*)d_in[4];
    const void*  src      = d_in[5];
    const void*  dst      = d_in[6];
    float*       out      = (float*)d_out;
    int E = in_sizes[5];
    if (E > MAX_E) E = MAX_E;

    float *agg_p, *t2_p;
    int   *cnt_p;
    cudaGetSymbolAddress((void**)&agg_p, g_agg);
    cudaGetSymbolAddress((void**)&t2_p,  g_t2);
    cudaGetSymbolAddress((void**)&cnt_p, g_cnt);

    cudaFuncSetAttribute(gemm_hmma_kernel,
                         cudaFuncAttributeMaxDynamicSharedMemorySize, SM_TOT);

    const int TB = 256;
    cudaMemsetAsync(cnt_p, 0, N_NODES * sizeof(int), 0);
    wconv_kernel<<<24, 256>>>(W1, W2);
    convcount_kernel<<<(E + TB - 1) / TB, TB>>>(dst, E);
    scan_pass1<<<SCAN_BLOCKS, 256>>>();
    scan_pass23<<<SCAN_BLOCKS, 256>>>();
    fill_kernel<<<(E + TB - 1) / TB, TB>>>(src, dst, E);

    int agg_blocks = (N_NODES * 32 + TB - 1) / TB;
    agg_kernel<<<agg_blocks, TB>>>(features, agg_p);
    gemm_hmma_kernel<<<(N_NODES + 127) / 128, 256, SM_TOT>>>(agg_p, b1, t2_p);
    agg64_kernel<<<agg_blocks, TB>>>(t2_p, b2, out);
}

// round 10
// speedup vs baseline: 1.3957x; 1.0412x over previous
#include <cuda_runtime.h>
#include <cuda_bf16.h>
#include <cuda_fp16.h>

#define N_NODES 100000
#define MAX_E   1600000
#define D       128
#define SCAN_BLOCKS ((N_NODES + 255) / 256)   // 391

typedef unsigned int u32;

// ---------------- device scratch ----------------------------------------------
__device__ int    g_cnt[N_NODES];
__device__ int    g_scan[SCAN_BLOCKS * 256];
__device__ int    g_bsum[512];
__device__ int    g_rowptr[N_NODES + 1];
__device__ int    g_cursor[N_NODES];
__device__ int    g_colidx[MAX_E];
__device__ __half g_Xh [(size_t)N_NODES * D];   // X in fp16 (gather source)
__device__ float  g_agg[(size_t)N_NODES * D];   // S(X), fp32
__device__ __half g_t2h[(size_t)N_NODES * 64];  // relu(S@W1+b1)@W2 in fp16

// W fragments in mma.sync register layout: [split][kstep][nfrag][lane] uint2
__device__ uint2 g_B1f[2 * 8 * 16 * 32];   // W1: N=128 -> 16 nfrags
__device__ uint2 g_B2f[2 * 8 * 8 * 32];    // W2: N=64  -> 8 nfrags

// ---------------- helpers -------------------------------------------------------
__device__ __forceinline__ u32 pack_bf16(float lo, float hi) {
    __nv_bfloat162 t = __floats2bfloat162_rn(lo, hi);   // .x = lo half
    return *(u32*)&t;
}
__device__ __forceinline__ void mma_bf16(float* c, const u32* a, u32 b0, u32 b1) {
    asm volatile(
        "mma.sync.aligned.m16n8k16.row.col.f32.bf16.bf16.f32 "
        "{%0,%1,%2,%3}, {%4,%5,%6,%7}, {%8,%9}, {%0,%1,%2,%3};"
        : "+f"(c[0]), "+f"(c[1]), "+f"(c[2]), "+f"(c[3])
        : "r"(a[0]), "r"(a[1]), "r"(a[2]), "r"(a[3]), "r"(b0), "r"(b1));
}
__device__ __forceinline__ int edge_idx(const void* p, int i, int is64) {
    return is64 ? (int)((const long long*)p)[i] : ((const int*)p)[i];
}
__device__ __forceinline__ float2 h2f(u32 h) {
    return __half22float2(*(__half2*)&h);
}

// ---------------- CSR build -----------------------------------------------------
__global__ void convcount_kernel(const void* __restrict__ dst, int E) {
    int v = ((const int*)dst)[(threadIdx.x & 255) * 2 + 1];
    int is64 = !__syncthreads_or(v != 0);
    int i = blockIdx.x * blockDim.x + threadIdx.x;
    if (i >= E) return;
    int d = edge_idx(dst, i, is64);
    if ((unsigned)d < N_NODES) atomicAdd(&g_cnt[d], 1);
}

__global__ void scan_pass1() {
    __shared__ int s[256];
    int t = threadIdx.x;
    int i = blockIdx.x * 256 + t;
    int v = (i < N_NODES) ? g_cnt[i] : 0;
    s[t] = v;
    __syncthreads();
#pragma unroll
    for (int off = 1; off < 256; off <<= 1) {
        int x = (t >= off) ? s[t - off] : 0;
        __syncthreads();
        s[t] += x;
        __syncthreads();
    }
    g_scan[i] = s[t];
    if (t == 255) g_bsum[blockIdx.x] = s[255];
}

__global__ void scan_pass23() {
    const int b = blockIdx.x, t = threadIdx.x;
    int x = 0;
    if (t < b)       x += g_bsum[t];
    if (t + 256 < b) x += g_bsum[t + 256];
#pragma unroll
    for (int o = 16; o > 0; o >>= 1) x += __shfl_down_sync(~0u, x, o);
    __shared__ int wsum[8];
    if ((t & 31) == 0) wsum[t >> 5] = x;
    __syncthreads();
    __shared__ int off;
    if (t == 0) {
        int s = 0;
#pragma unroll
        for (int w = 0; w < 8; w++) s += wsum[w];
        off = s;
    }
    __syncthreads();
    int i = b * 256 + t;
    if (i >= N_NODES) return;
    int incl = g_scan[i] + off;
    g_rowptr[i + 1] = incl;
    g_cursor[i] = incl - g_cnt[i];
    if (i == 0) g_rowptr[0] = 0;
}

__global__ void fill_kernel(const void* __restrict__ src,
                            const void* __restrict__ dst, int E) {
    int v = ((const int*)dst)[(threadIdx.x & 255) * 2 + 1];
    int is64 = !__syncthreads_or(v != 0);
    int i = blockIdx.x * blockDim.x + threadIdx.x;
    if (i >= E) return;
    unsigned d = (unsigned)edge_idx(dst, i, is64);
    unsigned s = (unsigned)edge_idx(src, i, is64);
    if (d >= N_NODES || s >= N_NODES) return;
    int pos = atomicAdd(&g_cursor[d], 1);
    g_colidx[pos] = (int)s;
}

// ---------------- X fp32 -> fp16 ---------------------------------------------------
__global__ void xconv_kernel(const float* __restrict__ X) {
    int i = blockIdx.x * blockDim.x + threadIdx.x;   // one float4 -> 2x half2
    if (i >= (N_NODES * D) / 4) return;
    float4 v = *(const float4*)(X + (size_t)i * 4);
    __half2 h0 = __floats2half2_rn(v.x, v.y);
    __half2 h1 = __floats2half2_rn(v.z, v.w);
    uint2 p;
    p.x = *(u32*)&h0; p.y = *(u32*)&h1;
    *(uint2*)(g_Xh + (size_t)i * 4) = p;
}

// ---------------- aggregations (fp16 gather, fp32 accumulate) --------------------
__global__ void agg_kernel_h(float* __restrict__ out) {
    int warp = (blockIdx.x * blockDim.x + threadIdx.x) >> 5;
    int lane = threadIdx.x & 31;
    if (warp >= N_NODES) return;
    int s = __ldg(&g_rowptr[warp]);
    int e = __ldg(&g_rowptr[warp + 1]);
    const __half* in = g_Xh;
    float4 acc = make_float4(0.f, 0.f, 0.f, 0.f);
    int i = s;
    for (; i + 4 <= e; i += 4) {
        int c0 = __ldg(&g_colidx[i + 0]);
        int c1 = __ldg(&g_colidx[i + 1]);
        int c2 = __ldg(&g_colidx[i + 2]);
        int c3 = __ldg(&g_colidx[i + 3]);
        uint2 v0 = __ldg((const uint2*)(in + (size_t)c0 * D) + lane);
        uint2 v1 = __ldg((const uint2*)(in + (size_t)c1 * D) + lane);
        uint2 v2 = __ldg((const uint2*)(in + (size_t)c2 * D) + lane);
        uint2 v3 = __ldg((const uint2*)(in + (size_t)c3 * D) + lane);
        float2 a0 = h2f(v0.x), b0 = h2f(v0.y);
        float2 a1 = h2f(v1.x), b1 = h2f(v1.y);
        float2 a2 = h2f(v2.x), b2 = h2f(v2.y);
        float2 a3 = h2f(v3.x), b3 = h2f(v3.y);
        acc.x += (a0.x + a1.x) + (a2.x + a3.x);
        acc.y += (a0.y + a1.y) + (a2.y + a3.y);
        acc.z += (b0.x + b1.x) + (b2.x + b3.x);
        acc.w += (b0.y + b1.y) + (b2.y + b3.y);
    }
    for (; i < e; i++) {
        int c = __ldg(&g_colidx[i]);
        uint2 v = __ldg((const uint2*)(in + (size_t)c * D) + lane);
        float2 a = h2f(v.x), b = h2f(v.y);
        acc.x += a.x; acc.y += a.y; acc.z += b.x; acc.w += b.y;
    }
    int cnt = e - s;
    float inv = 1.f / (float)(cnt > 1 ? cnt : 1);
    acc.x *= inv; acc.y *= inv; acc.z *= inv; acc.w *= inv;
    ((float4*)(out + (size_t)warp * D))[lane] = acc;
}

__global__ void agg64_kernel_h(const float* __restrict__ bias,
                               float* __restrict__ out) {
    int warp = (blockIdx.x * blockDim.x + threadIdx.x) >> 5;
    int lane = threadIdx.x & 31;
    if (warp >= N_NODES) return;
    int s = __ldg(&g_rowptr[warp]);
    int e = __ldg(&g_rowptr[warp + 1]);
    const __half* in = g_t2h;
    float2 acc = make_float2(0.f, 0.f);
    int i = s;
    for (; i + 4 <= e; i += 4) {
        int c0 = __ldg(&g_colidx[i + 0]);
        int c1 = __ldg(&g_colidx[i + 1]);
        int c2 = __ldg(&g_colidx[i + 2]);
        int c3 = __ldg(&g_colidx[i + 3]);
        u32 v0 = __ldg((const u32*)(in + (size_t)c0 * 64) + lane);
        u32 v1 = __ldg((const u32*)(in + (size_t)c1 * 64) + lane);
        u32 v2 = __ldg((const u32*)(in + (size_t)c2 * 64) + lane);
        u32 v3 = __ldg((const u32*)(in + (size_t)c3 * 64) + lane);
        float2 f0 = h2f(v0), f1 = h2f(v1), f2 = h2f(v2), f3 = h2f(v3);
        acc.x += (f0.x + f1.x) + (f2.x + f3.x);
        acc.y += (f0.y + f1.y) + (f2.y + f3.y);
    }
    for (; i < e; i++) {
        int c = __ldg(&g_colidx[i]);
        float2 f = h2f(__ldg((const u32*)(in + (size_t)c * 64) + lane));
        acc.x += f.x; acc.y += f.y;
    }
    int cnt = e - s;
    float inv = 1.f / (float)(cnt > 1 ? cnt : 1);
    float2 b = __ldg((const float2*)bias + lane);
    float2 o;
    o.x = acc.x * inv + b.x;
    o.y = acc.y * inv + b.y;
    ((float2*)(out + (size_t)warp * 64))[lane] = o;
}

// ---------------- W fp32 -> hi/lo bf16 mma fragments -----------------------------
__global__ void wconv_kernel(const float* __restrict__ W1, const float* __restrict__ W2) {
    int i = blockIdx.x * blockDim.x + threadIdx.x;
    if (i < 4096) {                          // W1: 8 ks x 16 nf x 32 lanes
        int lane = i & 31, nf = (i >> 5) & 15, ks = i >> 9;
        int k = ks * 16 + (lane & 3) * 2;
        int n = nf * 8 + (lane >> 2);
        float w00 = W1[k * 128 + n],       w01 = W1[(k + 1) * 128 + n];
        float w10 = W1[(k + 8) * 128 + n], w11 = W1[(k + 9) * 128 + n];
        float h00 = __bfloat162float(__float2bfloat16(w00));
        float h01 = __bfloat162float(__float2bfloat16(w01));
        float h10 = __bfloat162float(__float2bfloat16(w10));
        float h11 = __bfloat162float(__float2bfloat16(w11));
        uint2 hi, lo;
        hi.x = pack_bf16(h00, h01);          hi.y = pack_bf16(h10, h11);
        lo.x = pack_bf16(w00 - h00, w01 - h01);
        lo.y = pack_bf16(w10 - h10, w11 - h11);
        g_B1f[(ks * 16 + nf) * 32 + lane]       = hi;
        g_B1f[((8 + ks) * 16 + nf) * 32 + lane] = lo;
    } else if (i < 6144) {                   // W2: 8 ks x 8 nf x 32 lanes
        int j = i - 4096;
        int lane = j & 31, nf = (j >> 5) & 7, ks = j >> 8;
        int k = ks * 16 + (lane & 3) * 2;
        int n = nf * 8 + (lane >> 2);
        float w00 = W2[k * 64 + n],       w01 = W2[(k + 1) * 64 + n];
        float w10 = W2[(k + 8) * 64 + n], w11 = W2[(k + 9) * 64 + n];
        float h00 = __bfloat162float(__float2bfloat16(w00));
        float h01 = __bfloat162float(__float2bfloat16(w01));
        float h10 = __bfloat162float(__float2bfloat16(w10));
        float h11 = __bfloat162float(__float2bfloat16(w11));
        uint2 hi, lo;
        hi.x = pack_bf16(h00, h01);          hi.y = pack_bf16(h10, h11);
        lo.x = pack_bf16(w00 - h00, w01 - h01);
        lo.y = pack_bf16(w10 - h10, w11 - h11);
        g_B2f[(ks * 8 + nf) * 32 + lane]       = hi;
        g_B2f[((8 + ks) * 8 + nf) * 32 + lane] = lo;
    }
}

// ---------------- fused double GEMM via HMMA (3x bf16 split) ---------------------
#define ASTRIDE 68
#define SM_B1   0
#define SM_AHI  512
#define SM_ALO  (SM_AHI + 34816)
#define SM_BF1  (SM_ALO + 34816)
#define SM_BF2  (SM_BF1 + 65536)
#define SM_TOT  (SM_BF2 + 32768)             // 168448

__global__ void __launch_bounds__(256, 1)
gemm_hmma_kernel(const float* __restrict__ A, const float* __restrict__ b1) {
    extern __shared__ char smem[];
    float* b1s = (float*)(smem + SM_B1);
    u32*   Ahi = (u32*)(smem + SM_AHI);
    u32*   Alo = (u32*)(smem + SM_ALO);
    uint2* Bs1 = (uint2*)(smem + SM_BF1);
    uint2* Bs2 = (uint2*)(smem + SM_BF2);

    const int tid  = threadIdx.x;
    const int lane = tid & 31;
    const int wid  = tid >> 5;
    const int wm   = wid & 3;
    const int wn   = wid >> 2;
    const int m0   = blockIdx.x * 128;

    {
        const uint4* s1 = (const uint4*)g_B1f;
        const uint4* s2 = (const uint4*)g_B2f;
        uint4* d1 = (uint4*)Bs1;
        uint4* d2 = (uint4*)Bs2;
        for (int i = tid; i < 4096; i += 256) d1[i] = s1[i];
        for (int i = tid; i < 2048; i += 256) d2[i] = s2[i];
        if (tid < 32) ((float4*)b1s)[tid] = ((const float4*)b1)[tid];
    }

    for (int i = tid * 4; i < 16384; i += 1024) {
        int r = i >> 7, c = i & 127;
        float4 v = make_float4(0.f, 0.f, 0.f, 0.f);
        if (m0 + r < N_NODES)
            v = *(const float4*)&A[(size_t)(m0 + r) * 128 + c];
        float hx = __bfloat162float(__float2bfloat16(v.x));
        float hy = __bfloat162float(__float2bfloat16(v.y));
        float hz = __bfloat162float(__float2bfloat16(v.z));
        float hw = __bfloat162float(__float2bfloat16(v.w));
        uint2 hp, lp;
        hp.x = pack_bf16(hx, hy);             hp.y = pack_bf16(hz, hw);
        lp.x = pack_bf16(v.x - hx, v.y - hy); lp.y = pack_bf16(v.z - hz, v.w - hw);
        *(uint2*)&Ahi[r * ASTRIDE + (c >> 1)] = hp;
        *(uint2*)&Alo[r * ASTRIDE + (c >> 1)] = lp;
    }
    __syncthreads();

    // stage 1: D1 = A @ W1  (M128 x N128)
    float acc[2][8][4];
#pragma unroll
    for (int mf = 0; mf < 2; mf++)
#pragma unroll
        for (int nf = 0; nf < 8; nf++)
#pragma unroll
            for (int q = 0; q < 4; q++) acc[mf][nf][q] = 0.f;

    const int arow = (lane >> 2);
    const int acol = (lane & 3);
#pragma unroll
    for (int ks = 0; ks < 8; ks++) {
        int cb = ks * 8 + acol;
        u32 ah[2][4], al[2][4];
#pragma unroll
        for (int mf = 0; mf < 2; mf++) {
            int r = wm * 32 + mf * 16 + arow;
            ah[mf][0] = Ahi[r * ASTRIDE + cb];
            ah[mf][1] = Ahi[(r + 8) * ASTRIDE + cb];
            ah[mf][2] = Ahi[r * ASTRIDE + cb + 4];
            ah[mf][3] = Ahi[(r + 8) * ASTRIDE + cb + 4];
            al[mf][0] = Alo[r * ASTRIDE + cb];
            al[mf][1] = Alo[(r + 8) * ASTRIDE + cb];
            al[mf][2] = Alo[r * ASTRIDE + cb + 4];
            al[mf][3] = Alo[(r + 8) * ASTRIDE + cb + 4];
        }
#pragma unroll
        for (int nf = 0; nf < 8; nf++) {
            int nfg = wn * 8 + nf;
            uint2 bh = Bs1[(ks * 16 + nfg) * 32 + lane];
            uint2 bl = Bs1[((8 + ks) * 16 + nfg) * 32 + lane];
#pragma unroll
            for (int mf = 0; mf < 2; mf++) {
                mma_bf16(acc[mf][nf], ah[mf], bh.x, bh.y);
                mma_bf16(acc[mf][nf], ah[mf], bl.x, bl.y);
                mma_bf16(acc[mf][nf], al[mf], bh.x, bh.y);
            }
        }
    }
    __syncthreads();

    // epilogue 1: h1 = relu(D1 + b1) -> hi/lo bf16 back into A smem
#pragma unroll
    for (int mf = 0; mf < 2; mf++) {
#pragma unroll
        for (int nf = 0; nf < 8; nf++) {
            int r   = wm * 32 + mf * 16 + arow;
            int col = wn * 64 + nf * 8 + acol * 2;
            float bb0 = b1s[col], bb1 = b1s[col + 1];
            float x0 = fmaxf(acc[mf][nf][0] + bb0, 0.f);
            float x1 = fmaxf(acc[mf][nf][1] + bb1, 0.f);
            float x2 = fmaxf(acc[mf][nf][2] + bb0, 0.f);
            float x3 = fmaxf(acc[mf][nf][3] + bb1, 0.f);
            float h0 = __bfloat162float(__float2bfloat16(x0));
            float h1 = __bfloat162float(__float2bfloat16(x1));
            float h2 = __bfloat162float(__float2bfloat16(x2));
            float h3 = __bfloat162float(__float2bfloat16(x3));
            Ahi[r * ASTRIDE + (col >> 1)]       = pack_bf16(h0, h1);
            Alo[r * ASTRIDE + (col >> 1)]       = pack_bf16(x0 - h0, x1 - h1);
            Ahi[(r + 8) * ASTRIDE + (col >> 1)] = pack_bf16(h2, h3);
            Alo[(r + 8) * ASTRIDE + (col >> 1)] = pack_bf16(x2 - h2, x3 - h3);
        }
    }
    __syncthreads();

    // stage 2: t2 = h1 @ W2  (M128 x N64)
    float acc2[2][4][4];
#pragma unroll
    for (int mf = 0; mf < 2; mf++)
#pragma unroll
        for (int nf = 0; nf < 4; nf++)
#pragma unroll
            for (int q = 0; q < 4; q++) acc2[mf][nf][q] = 0.f;

#pragma unroll
    for (int ks = 0; ks < 8; ks++) {
        int cb = ks * 8 + acol;
        u32 ah[2][4], al[2][4];
#pragma unroll
        for (int mf = 0; mf < 2; mf++) {
            int r = wm * 32 + mf * 16 + arow;
            ah[mf][0] = Ahi[r * ASTRIDE + cb];
            ah[mf][1] = Ahi[(r + 8) * ASTRIDE + cb];
            ah[mf][2] = Ahi[r * ASTRIDE + cb + 4];
            ah[mf][3] = Ahi[(r + 8) * ASTRIDE + cb + 4];
            al[mf][0] = Alo[r * ASTRIDE + cb];
            al[mf][1] = Alo[(r + 8) * ASTRIDE + cb];
            al[mf][2] = Alo[r * ASTRIDE + cb + 4];
            al[mf][3] = Alo[(r + 8) * ASTRIDE + cb + 4];
        }
#pragma unroll
        for (int nf = 0; nf < 4; nf++) {
            int nfg = wn * 4 + nf;
            uint2 bh = Bs2[(ks * 8 + nfg) * 32 + lane];
            uint2 bl = Bs2[((8 + ks) * 8 + nfg) * 32 + lane];
#pragma unroll
            for (int mf = 0; mf < 2; mf++) {
                mma_bf16(acc2[mf][nf], ah[mf], bh.x, bh.y);
                mma_bf16(acc2[mf][nf], ah[mf], bl.x, bl.y);
                mma_bf16(acc2[mf][nf], al[mf], bh.x, bh.y);
            }
        }
    }

    // epilogue 2: write t2 as fp16
#pragma unroll
    for (int mf = 0; mf < 2; mf++) {
#pragma unroll
        for (int nf = 0; nf < 4; nf++) {
            int r   = m0 + wm * 32 + mf * 16 + arow;
            int col = wn * 32 + nf * 8 + acol * 2;
            if (r < N_NODES) {
                __half2 h = __floats2half2_rn(acc2[mf][nf][0], acc2[mf][nf][1]);
                *(u32*)&g_t2h[(size_t)r * 64 + col] = *(u32*)&h;
            }
            if (r + 8 < N_NODES) {
                __half2 h = __floats2half2_rn(acc2[mf][nf][2], acc2[mf][nf][3]);
                *(u32*)&g_t2h[(size_t)(r + 8) * 64 + col] = *(u32*)&h;
            }
        }
    }
}

// ---------------- launch ---------------------------------------------------------
extern "C" void kernel_launch(void* const* d_in, const int* in_sizes, int n_in,
                              void* d_out, int out_size) {
    const float* features = (const float*)d_in[0];
    const float* W1       = (const float*)d_in[1];
    const float* b1       = (const float*)d_in[2];
    const float* W2       = (const float*)d_in[3];
    const float* b2       = (const float*)d_in[4];
    const void*  src      = d_in[5];
    const void*  dst      = d_in[6];
    float*       out      = (float*)d_out;
    int E = in_sizes[5];
    if (E > MAX_E) E = MAX_E;

    float *agg_p;
    int   *cnt_p;
    cudaGetSymbolAddress((void**)&agg_p, g_agg);
    cudaGetSymbolAddress((void**)&cnt_p, g_cnt);

    cudaFuncSetAttribute(gemm_hmma_kernel,
                         cudaFuncAttributeMaxDynamicSharedMemorySize, SM_TOT);

    const int TB = 256;
    cudaMemsetAsync(cnt_p, 0, N_NODES * sizeof(int), 0);
    wconv_kernel<<<24, 256>>>(W1, W2);
    xconv_kernel<<<(N_NODES * D / 4 + TB - 1) / TB, TB>>>(features);
    convcount_kernel<<<(E + TB - 1) / TB, TB>>>(dst, E);
    scan_pass1<<<SCAN_BLOCKS, 256>>>();
    scan_pass23<<<SCAN_BLOCKS, 256>>>();
    fill_kernel<<<(E + TB - 1) / TB, TB>>>(src, dst, E);

    int agg_blocks = (N_NODES * 32 + TB - 1) / TB;
    agg_kernel_h<<<agg_blocks, TB>>>(agg_p);
    gemm_hmma_kernel<<<(N_NODES + 127) / 128, 256, SM_TOT>>>(agg_p, b1);
    agg64_kernel_h<<<agg_blocks, TB>>>(b2, out);
}

// round 11
// speedup vs baseline: 1.4721x; 1.0547x over previous
#include <cuda_runtime.h>
#include <cuda_bf16.h>
#include <cuda_fp16.h>

#define N_NODES 100000
#define MAX_E   1600000
#define D       128
#define SCAN_BLOCKS ((N_NODES + 255) / 256)   // 391

typedef unsigned int u32;

// ---------------- device scratch ----------------------------------------------
__device__ int            g_cnt[N_NODES];
__device__ int            g_scan[SCAN_BLOCKS * 256];
__device__ int            g_bsum[512];
__device__ int            g_rowptr[N_NODES + 1];
__device__ unsigned short g_rank[MAX_E];
__device__ int            g_colidx[MAX_E];
__device__ __half         g_Xh [(size_t)N_NODES * D];   // X in fp16
__device__ float          g_agg[(size_t)N_NODES * D];   // S(X), fp32
__device__ __half         g_t2h[(size_t)N_NODES * 64];  // relu(S@W1+b1)@W2 fp16

// W fragments in mma.sync register layout: [split][kstep][nfrag][lane] uint2
__device__ uint2 g_B1f[2 * 8 * 16 * 32];
__device__ uint2 g_B2f[2 * 8 * 8 * 32];

// ---------------- helpers -------------------------------------------------------
__device__ __forceinline__ u32 pack_bf16(float lo, float hi) {
    __nv_bfloat162 t = __floats2bfloat162_rn(lo, hi);
    return *(u32*)&t;
}
__device__ __forceinline__ void mma_bf16(float* c, const u32* a, u32 b0, u32 b1) {
    asm volatile(
        "mma.sync.aligned.m16n8k16.row.col.f32.bf16.bf16.f32 "
        "{%0,%1,%2,%3}, {%4,%5,%6,%7}, {%8,%9}, {%0,%1,%2,%3};"
        : "+f"(c[0]), "+f"(c[1]), "+f"(c[2]), "+f"(c[3])
        : "r"(a[0]), "r"(a[1]), "r"(a[2]), "r"(a[3]), "r"(b0), "r"(b1));
}
__device__ __forceinline__ int edge_idx(const void* p, int i, int is64) {
    return is64 ? (int)((const long long*)p)[i] : ((const int*)p)[i];
}
__device__ __forceinline__ float2 h2f(u32 h) {
    return __half22float2(*(__half2*)&h);
}

// ---------------- CSR build -----------------------------------------------------
// count + record per-edge rank within its dst (the atomic's return value)
__global__ void convcount_kernel(const void* __restrict__ dst, int E) {
    int v = ((const int*)dst)[(threadIdx.x & 255) * 2 + 1];
    int is64 = !__syncthreads_or(v != 0);
    int i = blockIdx.x * blockDim.x + threadIdx.x;
    if (i >= E) return;
    int d = edge_idx(dst, i, is64);
    if ((unsigned)d < N_NODES)
        g_rank[i] = (unsigned short)atomicAdd(&g_cnt[d], 1);
}

__global__ void scan_pass1() {
    __shared__ int s[256];
    int t = threadIdx.x;
    int i = blockIdx.x * 256 + t;
    int v = (i < N_NODES) ? g_cnt[i] : 0;
    s[t] = v;
    __syncthreads();
#pragma unroll
    for (int off = 1; off < 256; off <<= 1) {
        int x = (t >= off) ? s[t - off] : 0;
        __syncthreads();
        s[t] += x;
        __syncthreads();
    }
    g_scan[i] = s[t];
    if (t == 255) g_bsum[blockIdx.x] = s[255];
}

__global__ void scan_pass23() {
    const int b = blockIdx.x, t = threadIdx.x;
    int x = 0;
    if (t < b)       x += g_bsum[t];
    if (t + 256 < b) x += g_bsum[t + 256];
#pragma unroll
    for (int o = 16; o > 0; o >>= 1) x += __shfl_down_sync(~0u, x, o);
    __shared__ int wsum[8];
    if ((t & 31) == 0) wsum[t >> 5] = x;
    __syncthreads();
    __shared__ int off;
    if (t == 0) {
        int s = 0;
#pragma unroll
        for (int w = 0; w < 8; w++) s += wsum[w];
        off = s;
    }
    __syncthreads();
    int i = b * 256 + t;
    if (i >= N_NODES) return;
    g_rowptr[i + 1] = g_scan[i] + off;
    if (i == 0) g_rowptr[0] = 0;
}

// atomic-free fill: slot = rowptr[d] + rank[i] (rowptr fits L2 -> cheap gather)
__global__ void fill_kernel(const void* __restrict__ src,
                            const void* __restrict__ dst, int E) {
    int v = ((const int*)dst)[(threadIdx.x & 255) * 2 + 1];
    int is64 = !__syncthreads_or(v != 0);
    int i = blockIdx.x * blockDim.x + threadIdx.x;
    if (i >= E) return;
    unsigned d = (unsigned)edge_idx(dst, i, is64);
    if (d >= N_NODES) return;
    unsigned s = (unsigned)edge_idx(src, i, is64);
    if (s >= N_NODES) s = 0;   // reference inputs are always in range
    g_colidx[__ldg(&g_rowptr[d]) + (int)g_rank[i]] = (int)s;
}

// ---------------- X fp32 -> fp16 ---------------------------------------------------
__global__ void xconv_kernel(const float* __restrict__ X) {
    int i = blockIdx.x * blockDim.x + threadIdx.x;
    if (i >= (N_NODES * D) / 4) return;
    float4 v = *(const float4*)(X + (size_t)i * 4);
    __half2 h0 = __floats2half2_rn(v.x, v.y);
    __half2 h1 = __floats2half2_rn(v.z, v.w);
    uint2 p;
    p.x = *(u32*)&h0; p.y = *(u32*)&h1;
    *(uint2*)(g_Xh + (size_t)i * 4) = p;
}

// ---------------- aggregations (fp16 gather, fp32 accumulate, 8-deep MLP) --------
__global__ void agg_kernel_h(float* __restrict__ out) {
    int warp = (blockIdx.x * blockDim.x + threadIdx.x) >> 5;
    int lane = threadIdx.x & 31;
    if (warp >= N_NODES) return;
    int s = __ldg(&g_rowptr[warp]);
    int e = __ldg(&g_rowptr[warp + 1]);
    const __half* in = g_Xh;
    float4 acc = make_float4(0.f, 0.f, 0.f, 0.f);
    int i = s;
    for (; i + 8 <= e; i += 8) {
        uint2 v[8];
#pragma unroll
        for (int j = 0; j < 8; j++) {
            int c = __ldg(&g_colidx[i + j]);
            v[j] = __ldg((const uint2*)(in + (size_t)c * D) + lane);
        }
#pragma unroll
        for (int j = 0; j < 8; j++) {
            float2 a = h2f(v[j].x), b = h2f(v[j].y);
            acc.x += a.x; acc.y += a.y; acc.z += b.x; acc.w += b.y;
        }
    }
    for (; i + 4 <= e; i += 4) {
        uint2 v[4];
#pragma unroll
        for (int j = 0; j < 4; j++) {
            int c = __ldg(&g_colidx[i + j]);
            v[j] = __ldg((const uint2*)(in + (size_t)c * D) + lane);
        }
#pragma unroll
        for (int j = 0; j < 4; j++) {
            float2 a = h2f(v[j].x), b = h2f(v[j].y);
            acc.x += a.x; acc.y += a.y; acc.z += b.x; acc.w += b.y;
        }
    }
    for (; i < e; i++) {
        int c = __ldg(&g_colidx[i]);
        uint2 v = __ldg((const uint2*)(in + (size_t)c * D) + lane);
        float2 a = h2f(v.x), b = h2f(v.y);
        acc.x += a.x; acc.y += a.y; acc.z += b.x; acc.w += b.y;
    }
    int cnt = e - s;
    float inv = 1.f / (float)(cnt > 1 ? cnt : 1);
    acc.x *= inv; acc.y *= inv; acc.z *= inv; acc.w *= inv;
    ((float4*)(out + (size_t)warp * D))[lane] = acc;
}

__global__ void agg64_kernel_h(const float* __restrict__ bias,
                               float* __restrict__ out) {
    int warp = (blockIdx.x * blockDim.x + threadIdx.x) >> 5;
    int lane = threadIdx.x & 31;
    if (warp >= N_NODES) return;
    int s = __ldg(&g_rowptr[warp]);
    int e = __ldg(&g_rowptr[warp + 1]);
    const __half* in = g_t2h;
    float2 acc = make_float2(0.f, 0.f);
    int i = s;
    for (; i + 8 <= e; i += 8) {
        u32 v[8];
#pragma unroll
        for (int j = 0; j < 8; j++) {
            int c = __ldg(&g_colidx[i + j]);
            v[j] = __ldg((const u32*)(in + (size_t)c * 64) + lane);
        }
#pragma unroll
        for (int j = 0; j < 8; j++) {
            float2 f = h2f(v[j]);
            acc.x += f.x; acc.y += f.y;
        }
    }
    for (; i + 4 <= e; i += 4) {
        u32 v[4];
#pragma unroll
        for (int j = 0; j < 4; j++) {
            int c = __ldg(&g_colidx[i + j]);
            v[j] = __ldg((const u32*)(in + (size_t)c * 64) + lane);
        }
#pragma unroll
        for (int j = 0; j < 4; j++) {
            float2 f = h2f(v[j]);
            acc.x += f.x; acc.y += f.y;
        }
    }
    for (; i < e; i++) {
        int c = __ldg(&g_colidx[i]);
        float2 f = h2f(__ldg((const u32*)(in + (size_t)c * 64) + lane));
        acc.x += f.x; acc.y += f.y;
    }
    int cnt = e - s;
    float inv = 1.f / (float)(cnt > 1 ? cnt : 1);
    float2 b = __ldg((const float2*)bias + lane);
    float2 o;
    o.x = acc.x * inv + b.x;
    o.y = acc.y * inv + b.y;
    ((float2*)(out + (size_t)warp * 64))[lane] = o;
}

// ---------------- W fp32 -> hi/lo bf16 mma fragments -----------------------------
__global__ void wconv_kernel(const float* __restrict__ W1, const float* __restrict__ W2) {
    int i = blockIdx.x * blockDim.x + threadIdx.x;
    if (i < 4096) {
        int lane = i & 31, nf = (i >> 5) & 15, ks = i >> 9;
        int k = ks * 16 + (lane & 3) * 2;
        int n = nf * 8 + (lane >> 2);
        float w00 = W1[k * 128 + n],       w01 = W1[(k + 1) * 128 + n];
        float w10 = W1[(k + 8) * 128 + n], w11 = W1[(k + 9) * 128 + n];
        float h00 = __bfloat162float(__float2bfloat16(w00));
        float h01 = __bfloat162float(__float2bfloat16(w01));
        float h10 = __bfloat162float(__float2bfloat16(w10));
        float h11 = __bfloat162float(__float2bfloat16(w11));
        uint2 hi, lo;
        hi.x = pack_bf16(h00, h01);          hi.y = pack_bf16(h10, h11);
        lo.x = pack_bf16(w00 - h00, w01 - h01);
        lo.y = pack_bf16(w10 - h10, w11 - h11);
        g_B1f[(ks * 16 + nf) * 32 + lane]       = hi;
        g_B1f[((8 + ks) * 16 + nf) * 32 + lane] = lo;
    } else if (i < 6144) {
        int j = i - 4096;
        int lane = j & 31, nf = (j >> 5) & 7, ks = j >> 8;
        int k = ks * 16 + (lane & 3) * 2;
        int n = nf * 8 + (lane >> 2);
        float w00 = W2[k * 64 + n],       w01 = W2[(k + 1) * 64 + n];
        float w10 = W2[(k + 8) * 64 + n], w11 = W2[(k + 9) * 64 + n];
        float h00 = __bfloat162float(__float2bfloat16(w00));
        float h01 = __bfloat162float(__float2bfloat16(w01));
        float h10 = __bfloat162float(__float2bfloat16(w10));
        float h11 = __bfloat162float(__float2bfloat16(w11));
        uint2 hi, lo;
        hi.x = pack_bf16(h00, h01);          hi.y = pack_bf16(h10, h11);
        lo.x = pack_bf16(w00 - h00, w01 - h01);
        lo.y = pack_bf16(w10 - h10, w11 - h11);
        g_B2f[(ks * 8 + nf) * 32 + lane]       = hi;
        g_B2f[((8 + ks) * 8 + nf) * 32 + lane] = lo;
    }
}

// ---------------- fused double GEMM via HMMA (3x bf16 split) ---------------------
#define ASTRIDE 68
#define SM_B1   0
#define SM_AHI  512
#define SM_ALO  (SM_AHI + 34816)
#define SM_BF1  (SM_ALO + 34816)
#define SM_BF2  (SM_BF1 + 65536)
#define SM_TOT  (SM_BF2 + 32768)             // 168448

__global__ void __launch_bounds__(256, 1)
gemm_hmma_kernel(const float* __restrict__ A, const float* __restrict__ b1) {
    extern __shared__ char smem[];
    float* b1s = (float*)(smem + SM_B1);
    u32*   Ahi = (u32*)(smem + SM_AHI);
    u32*   Alo = (u32*)(smem + SM_ALO);
    uint2* Bs1 = (uint2*)(smem + SM_BF1);
    uint2* Bs2 = (uint2*)(smem + SM_BF2);

    const int tid  = threadIdx.x;
    const int lane = tid & 31;
    const int wid  = tid >> 5;
    const int wm   = wid & 3;
    const int wn   = wid >> 2;
    const int m0   = blockIdx.x * 128;

    {
        const uint4* s1 = (const uint4*)g_B1f;
        const uint4* s2 = (const uint4*)g_B2f;
        uint4* d1 = (uint4*)Bs1;
        uint4* d2 = (uint4*)Bs2;
        for (int i = tid; i < 4096; i += 256) d1[i] = s1[i];
        for (int i = tid; i < 2048; i += 256) d2[i] = s2[i];
        if (tid < 32) ((float4*)b1s)[tid] = ((const float4*)b1)[tid];
    }

    for (int i = tid * 4; i < 16384; i += 1024) {
        int r = i >> 7, c = i & 127;
        float4 v = make_float4(0.f, 0.f, 0.f, 0.f);
        if (m0 + r < N_NODES)
            v = *(const float4*)&A[(size_t)(m0 + r) * 128 + c];
        float hx = __bfloat162float(__float2bfloat16(v.x));
        float hy = __bfloat162float(__float2bfloat16(v.y));
        float hz = __bfloat162float(__float2bfloat16(v.z));
        float hw = __bfloat162float(__float2bfloat16(v.w));
        uint2 hp, lp;
        hp.x = pack_bf16(hx, hy);             hp.y = pack_bf16(hz, hw);
        lp.x = pack_bf16(v.x - hx, v.y - hy); lp.y = pack_bf16(v.z - hz, v.w - hw);
        *(uint2*)&Ahi[r * ASTRIDE + (c >> 1)] = hp;
        *(uint2*)&Alo[r * ASTRIDE + (c >> 1)] = lp;
    }
    __syncthreads();

    // stage 1: D1 = A @ W1  (M128 x N128)
    float acc[2][8][4];
#pragma unroll
    for (int mf = 0; mf < 2; mf++)
#pragma unroll
        for (int nf = 0; nf < 8; nf++)
#pragma unroll
            for (int q = 0; q < 4; q++) acc[mf][nf][q] = 0.f;

    const int arow = (lane >> 2);
    const int acol = (lane & 3);
#pragma unroll
    for (int ks = 0; ks < 8; ks++) {
        int cb = ks * 8 + acol;
        u32 ah[2][4], al[2][4];
#pragma unroll
        for (int mf = 0; mf < 2; mf++) {
            int r = wm * 32 + mf * 16 + arow;
            ah[mf][0] = Ahi[r * ASTRIDE + cb];
            ah[mf][1] = Ahi[(r + 8) * ASTRIDE + cb];
            ah[mf][2] = Ahi[r * ASTRIDE + cb + 4];
            ah[mf][3] = Ahi[(r + 8) * ASTRIDE + cb + 4];
            al[mf][0] = Alo[r * ASTRIDE + cb];
            al[mf][1] = Alo[(r + 8) * ASTRIDE + cb];
            al[mf][2] = Alo[r * ASTRIDE + cb + 4];
            al[mf][3] = Alo[(r + 8) * ASTRIDE + cb + 4];
        }
#pragma unroll
        for (int nf = 0; nf < 8; nf++) {
            int nfg = wn * 8 + nf;
            uint2 bh = Bs1[(ks * 16 + nfg) * 32 + lane];
            uint2 bl = Bs1[((8 + ks) * 16 + nfg) * 32 + lane];
#pragma unroll
            for (int mf = 0; mf < 2; mf++) {
                mma_bf16(acc[mf][nf], ah[mf], bh.x, bh.y);
                mma_bf16(acc[mf][nf], ah[mf], bl.x, bl.y);
                mma_bf16(acc[mf][nf], al[mf], bh.x, bh.y);
            }
        }
    }
    __syncthreads();

    // epilogue 1: h1 = relu(D1 + b1) -> hi/lo bf16 back into A smem
#pragma unroll
    for (int mf = 0; mf < 2; mf++) {
#pragma unroll
        for (int nf = 0; nf < 8; nf++) {
            int r   = wm * 32 + mf * 16 + arow;
            int col = wn * 64 + nf * 8 + acol * 2;
            float bb0 = b1s[col], bb1 = b1s[col + 1];
            float x0 = fmaxf(acc[mf][nf][0] + bb0, 0.f);
            float x1 = fmaxf(acc[mf][nf][1] + bb1, 0.f);
            float x2 = fmaxf(acc[mf][nf][2] + bb0, 0.f);
            float x3 = fmaxf(acc[mf][nf][3] + bb1, 0.f);
            float h0 = __bfloat162float(__float2bfloat16(x0));
            float h1 = __bfloat162float(__float2bfloat16(x1));
            float h2 = __bfloat162float(__float2bfloat16(x2));
            float h3 = __bfloat162float(__float2bfloat16(x3));
            Ahi[r * ASTRIDE + (col >> 1)]       = pack_bf16(h0, h1);
            Alo[r * ASTRIDE + (col >> 1)]       = pack_bf16(x0 - h0, x1 - h1);
            Ahi[(r + 8) * ASTRIDE + (col >> 1)] = pack_bf16(h2, h3);
            Alo[(r + 8) * ASTRIDE + (col >> 1)] = pack_bf16(x2 - h2, x3 - h3);
        }
    }
    __syncthreads();

    // stage 2: t2 = h1 @ W2  (M128 x N64)
    float acc2[2][4][4];
#pragma unroll
    for (int mf = 0; mf < 2; mf++)
#pragma unroll
        for (int nf = 0; nf < 4; nf++)
#pragma unroll
            for (int q = 0; q < 4; q++) acc2[mf][nf][q] = 0.f;

#pragma unroll
    for (int ks = 0; ks < 8; ks++) {
        int cb = ks * 8 + acol;
        u32 ah[2][4], al[2][4];
#pragma unroll
        for (int mf = 0; mf < 2; mf++) {
            int r = wm * 32 + mf * 16 + arow;
            ah[mf][0] = Ahi[r * ASTRIDE + cb];
            ah[mf][1] = Ahi[(r + 8) * ASTRIDE + cb];
            ah[mf][2] = Ahi[r * ASTRIDE + cb + 4];
            ah[mf][3] = Ahi[(r + 8) * ASTRIDE + cb + 4];
            al[mf][0] = Alo[r * ASTRIDE + cb];
            al[mf][1] = Alo[(r + 8) * ASTRIDE + cb];
            al[mf][2] = Alo[r * ASTRIDE + cb + 4];
            al[mf][3] = Alo[(r + 8) * ASTRIDE + cb + 4];
        }
#pragma unroll
        for (int nf = 0; nf < 4; nf++) {
            int nfg = wn * 4 + nf;
            uint2 bh = Bs2[(ks * 8 + nfg) * 32 + lane];
            uint2 bl = Bs2[((8 + ks) * 8 + nfg) * 32 + lane];
#pragma unroll
            for (int mf = 0; mf < 2; mf++) {
                mma_bf16(acc2[mf][nf], ah[mf], bh.x, bh.y);
                mma_bf16(acc2[mf][nf], ah[mf], bl.x, bl.y);
                mma_bf16(acc2[mf][nf], al[mf], bh.x, bh.y);
            }
        }
    }

    // epilogue 2: write t2 as fp16
#pragma unroll
    for (int mf = 0; mf < 2; mf++) {
#pragma unroll
        for (int nf = 0; nf < 4; nf++) {
            int r   = m0 + wm * 32 + mf * 16 + arow;
            int col = wn * 32 + nf * 8 + acol * 2;
            if (r < N_NODES) {
                __half2 h = __floats2half2_rn(acc2[mf][nf][0], acc2[mf][nf][1]);
                *(u32*)&g_t2h[(size_t)r * 64 + col] = *(u32*)&h;
            }
            if (r + 8 < N_NODES) {
                __half2 h = __floats2half2_rn(acc2[mf][nf][2], acc2[mf][nf][3]);
                *(u32*)&g_t2h[(size_t)(r + 8) * 64 + col] = *(u32*)&h;
            }
        }
    }
}

// ---------------- launch ---------------------------------------------------------
extern "C" void kernel_launch(void* const* d_in, const int* in_sizes, int n_in,
                              void* d_out, int out_size) {
    const float* features = (const float*)d_in[0];
    const float* W1       = (const float*)d_in[1];
    const float* b1       = (const float*)d_in[2];
    const float* W2       = (const float*)d_in[3];
    const float* b2       = (const float*)d_in[4];
    const void*  src      = d_in[5];
    const void*  dst      = d_in[6];
    float*       out      = (float*)d_out;
    int E = in_sizes[5];
    if (E > MAX_E) E = MAX_E;

    float *agg_p;
    int   *cnt_p;
    cudaGetSymbolAddress((void**)&agg_p, g_agg);
    cudaGetSymbolAddress((void**)&cnt_p, g_cnt);

    cudaFuncSetAttribute(gemm_hmma_kernel,
                         cudaFuncAttributeMaxDynamicSharedMemorySize, SM_TOT);

    cudaStream_t s1;
    cudaStreamCreateWithFlags(&s1, cudaStreamNonBlocking);
    cudaEvent_t evFork, evJoin;
    cudaEventCreateWithFlags(&evFork, cudaEventDisableTiming);
    cudaEventCreateWithFlags(&evJoin, cudaEventDisableTiming);

    const int TB = 256;
    // branch A (s1): CSR build (rank-based, atomic only in count)
    cudaMemsetAsync(cnt_p, 0, N_NODES * sizeof(int), 0);
    cudaEventRecord(evFork, 0);
    cudaStreamWaitEvent(s1, evFork, 0);
    convcount_kernel<<<(E + TB - 1) / TB, TB, 0, s1>>>(dst, E);
    scan_pass1<<<SCAN_BLOCKS, 256, 0, s1>>>();
    scan_pass23<<<SCAN_BLOCKS, 256, 0, s1>>>();
    fill_kernel<<<(E + TB - 1) / TB, TB, 0, s1>>>(src, dst, E);
    cudaEventRecord(evJoin, s1);

    // branch B (main): weight fragments + fp16 feature conversion
    wconv_kernel<<<24, 256>>>(W1, W2);
    xconv_kernel<<<(N_NODES * D / 4 + TB - 1) / TB, TB>>>(features);

    // join, then compute pipeline
    cudaStreamWaitEvent(0, evJoin, 0);
    int agg_blocks = (N_NODES * 32 + TB - 1) / TB;
    agg_kernel_h<<<agg_blocks, TB>>>(agg_p);
    gemm_hmma_kernel<<<(N_NODES + 127) / 128, 256, SM_TOT>>>(agg_p, b1);
    agg64_kernel_h<<<agg_blocks, TB>>>(b2, out);
}